// round 4
// baseline (speedup 1.0000x reference)
#include <cuda_runtime.h>

typedef unsigned long long u64;

// ---------------- packed f32x2 helpers (sm_10x) ----------------
__device__ __forceinline__ u64 ffma2(u64 a, u64 b, u64 c) {
    u64 d;
    asm("fma.rn.f32x2 %0, %1, %2, %3;" : "=l"(d) : "l"(a), "l"(b), "l"(c));
    return d;
}
__device__ __forceinline__ u64 pack2(float lo, float hi) {
    u64 r;
    asm("mov.b64 %0, {%1, %2};" : "=l"(r) : "f"(lo), "f"(hi));
    return r;
}
__device__ __forceinline__ void unpack2(u64 v, float& lo, float& hi) {
    asm("mov.b64 {%0, %1}, %2;" : "=f"(lo), "=f"(hi) : "l"(v));
}
__device__ __forceinline__ float tanh_ap(float x) {
    float y;
    asm("tanh.approx.f32 %0, %1;" : "=f"(y) : "f"(x));
    return y;
}
__device__ __forceinline__ u64 tanh2(u64 v) {
    float lo, hi;
    unpack2(v, lo, hi);
    return pack2(tanh_ap(lo), tanh_ap(hi));
}

// ---------------- constant weight table (u64 units, weights duplicated (w,w)) ----------------
// All matrix offsets AND bias offsets are even, all IN dims even -> every
// weight pair is one aligned ld.const.v2.u64 (LDC.128).
enum {
    O_W1 = 0,           // 16x8  = 128
    O_B1 = 128,         // 16
    O_W2 = 144,         // 16x16 = 256
    O_B2 = 400,         // 16
    O_W3 = 416,         // 12x16 = 192
    O_B3 = 608,         // 12
    O_W4 = 620,         // 8x12  = 96
    O_B4 = 716,         // 8
    O_W5 = 724,         // 4x8   = 32
    O_B5 = 756,         // 4
    O_WH = 760,         // 4x4   = 16
    O_BH = 776,         // 4
    W_TOTAL = 780
};

struct CParams {
    union {
        u64        W[W_TOTAL];
        ulonglong2 W2[W_TOTAL / 2];
    };
    float F[21];        // Wf(18) + bf(2) + (-gamma*log2e)(1)
    float pad[3];
};

__constant__ CParams cP;
__device__ CParams gScratch;

#define LOG2E 1.4426950408889634f
#define LN2   0.6931471805599453f

// ---------------- prep kernel: build duplicated table in device scratch ----------------
__global__ void prep_kernel(
    const float* __restrict__ W1, const float* __restrict__ b1,
    const float* __restrict__ W2, const float* __restrict__ b2,
    const float* __restrict__ W3, const float* __restrict__ b3,
    const float* __restrict__ W4, const float* __restrict__ b4,
    const float* __restrict__ W5, const float* __restrict__ b5,
    const float* __restrict__ Wh, const float* __restrict__ bh,
    const float* __restrict__ Wf, const float* __restrict__ bf,
    const float* __restrict__ gamma)
{
    int tid = threadIdx.x;
#define CP_(off, src, n)                                       \
    for (int i = tid; i < (n); i += blockDim.x) {              \
        float f = (src)[i];                                    \
        gScratch.W[(off) + i] = pack2(f, f);                   \
    }
    CP_(O_W1, W1, 128); CP_(O_B1, b1, 16);
    CP_(O_W2, W2, 256); CP_(O_B2, b2, 16);
    CP_(O_W3, W3, 192); CP_(O_B3, b3, 12);
    CP_(O_W4, W4, 96);  CP_(O_B4, b4, 8);
    CP_(O_W5, W5, 32);  CP_(O_B5, b5, 4);
    CP_(O_WH, Wh, 16);  CP_(O_BH, bh, 4);
#undef CP_
    if (tid < 18) gScratch.F[tid] = Wf[tid];
    if (tid == 18) gScratch.F[18] = bf[0];
    if (tid == 19) gScratch.F[19] = bf[1];
    if (tid == 20) gScratch.F[20] = -gamma[0] * LOG2E;
}

// ---------------- dense layer: vector constant loads, full unroll ----------------
template <int OFF_W, int OFF_B, int IN, int OUT, bool ACT>
__device__ __forceinline__ void layerfn(const u64* __restrict__ in, u64* __restrict__ out) {
#pragma unroll
    for (int j = 0; j < OUT; j++) {
        u64 a = cP.W[OFF_B + j];
#pragma unroll
        for (int i = 0; i < IN; i += 2) {
            ulonglong2 w = cP.W2[(OFF_W + j * IN + i) / 2];   // one LDC.128
            a = ffma2(in[i], w.x, a);
            a = ffma2(in[i + 1], w.y, a);
        }
        if (ACT) a = tanh2(a);
        out[j] = a;
    }
}

__global__ __launch_bounds__(128, 6) void qcnn_kernel(
    const float* __restrict__ x, float* __restrict__ out, int nb)
{
    int t = blockIdx.x * blockDim.x + threadIdx.x;   // < 2^20, int is safe
    int base = t * 2;                                // sample index, < 2^21
    if (base >= nb) return;
    const bool full = (base + 2 <= nb);

    // ---- load 2 samples (clamped for the tail) ----
    int i1 = (base + 1 <= nb - 1) ? base + 1 : nb - 1;
    const float4* p0 = (const float4*)(x + (size_t)base * 8);
    const float4* p1 = (const float4*)(x + (size_t)i1 * 8);
    float4 a0 = p0[0], a1 = p0[1];
    float4 c0 = p1[0], c1 = p1[1];

    u64 A[16], B[16];
    A[0] = pack2(a0.x, c0.x); A[1] = pack2(a0.y, c0.y);
    A[2] = pack2(a0.z, c0.z); A[3] = pack2(a0.w, c0.w);
    A[4] = pack2(a1.x, c1.x); A[5] = pack2(a1.y, c1.y);
    A[6] = pack2(a1.z, c1.z); A[7] = pack2(a1.w, c1.w);

    layerfn<O_W1, O_B1, 8,  16, true >(A, B);
    layerfn<O_W2, O_B2, 16, 16, true >(B, A);
    layerfn<O_W3, O_B3, 16, 12, true >(A, B);
    layerfn<O_W4, O_B4, 12, 8,  true >(B, A);
    layerfn<O_W5, O_B5, 8,  4,  true >(A, B);
    layerfn<O_WH, O_BH, 4,  4,  false>(B, A);   // cls_out in A[0..3]

    // ---- tail: RBF feature + final linear + log_softmax (scalar per sample) ----
    float cls[2][4];
#pragma unroll
    for (int j = 0; j < 4; j++) unpack2(A[j], cls[0][j], cls[1][j]);

    const float ngl2 = cP.F[20];
    float r[2][2];
#pragma unroll
    for (int s = 0; s < 2; s++) {
        float c0s = cls[s][0], c1s = cls[s][1], c2s = cls[s][2], c3s = cls[s][3];
        float s2 = fmaf(c0s, c0s, fmaf(c1s, c1s, fmaf(c2s, c2s, c3s * c3s)));
        float k = exp2f(s2 * ngl2);                         // exp(-gamma*s2)
        float o0 = cP.F[18];
        o0 = fmaf(cP.F[0], c0s, o0); o0 = fmaf(cP.F[1], c1s, o0);
        o0 = fmaf(cP.F[2], c2s, o0); o0 = fmaf(cP.F[3], c3s, o0);
        o0 = fmaf(cP.F[8], k, o0);
        float o1 = cP.F[19];
        o1 = fmaf(cP.F[9],  c0s, o1); o1 = fmaf(cP.F[10], c1s, o1);
        o1 = fmaf(cP.F[11], c2s, o1); o1 = fmaf(cP.F[12], c3s, o1);
        o1 = fmaf(cP.F[17], k, o1);

        float m  = fmaxf(o0, o1);
        float mn = fminf(o0, o1);
        float tt = exp2f((mn - m) * LOG2E);
        float lg; asm("lg2.approx.f32 %0, %1;" : "=f"(lg) : "f"(1.0f + tt));
        float lse = m + lg * LN2;
        r[s][0] = o0 - lse;
        r[s][1] = o1 - lse;
    }

    if (full) {
        float4 v = make_float4(r[0][0], r[0][1], r[1][0], r[1][1]);
        *(float4*)(out + (size_t)base * 2) = v;
    } else {
        if (base < nb)     { out[base * 2]     = r[0][0]; out[base * 2 + 1] = r[0][1]; }
        if (base + 1 < nb) { out[base * 2 + 2] = r[1][0]; out[base * 2 + 3] = r[1][1]; }
    }
}

extern "C" void kernel_launch(void* const* d_in, const int* in_sizes, int n_in,
                              void* d_out, int out_size) {
    const float* x  = (const float*)d_in[0];
    const float* W1 = (const float*)d_in[1];
    const float* b1 = (const float*)d_in[2];
    const float* W2 = (const float*)d_in[3];
    const float* b2 = (const float*)d_in[4];
    const float* W3 = (const float*)d_in[5];
    const float* b3 = (const float*)d_in[6];
    const float* W4 = (const float*)d_in[7];
    const float* b4 = (const float*)d_in[8];
    const float* W5 = (const float*)d_in[9];
    const float* b5 = (const float*)d_in[10];
    const float* Wh = (const float*)d_in[11];
    const float* bh = (const float*)d_in[12];
    const float* Wf = (const float*)d_in[13];
    const float* bf = (const float*)d_in[14];
    const float* gm = (const float*)d_in[15];

    // 1) build duplicated weight table in device scratch
    prep_kernel<<<1, 256>>>(W1, b1, W2, b2, W3, b3, W4, b4, W5, b5,
                            Wh, bh, Wf, bf, gm);

    // 2) move it into the constant bank (D2D async copy — graph-capturable)
    void* scratch_addr = nullptr;
    cudaGetSymbolAddress(&scratch_addr, gScratch);
    cudaMemcpyToSymbolAsync(cP, scratch_addr, sizeof(CParams), 0,
                            cudaMemcpyDeviceToDevice, 0);

    // 3) main kernel
    int nb = in_sizes[0] / 8;
    int threads = 128;
    int spb = threads * 2;
    int blocks = (nb + spb - 1) / spb;
    qcnn_kernel<<<blocks, threads>>>(x, (float*)d_out, nb);
}

// round 5
// speedup vs baseline: 1.1453x; 1.1453x over previous
#include <cuda_runtime.h>

typedef unsigned long long u64;

// ---------------- packed f32x2 helpers (sm_10x) ----------------
__device__ __forceinline__ u64 ffma2(u64 a, u64 b, u64 c) {
    u64 d;
    asm("fma.rn.f32x2 %0, %1, %2, %3;" : "=l"(d) : "l"(a), "l"(b), "l"(c));
    return d;
}
__device__ __forceinline__ u64 pack2(float lo, float hi) {
    u64 r;
    asm("mov.b64 %0, {%1, %2};" : "=l"(r) : "f"(lo), "f"(hi));
    return r;
}
__device__ __forceinline__ void unpack2(u64 v, float& lo, float& hi) {
    asm("mov.b64 {%0, %1}, %2;" : "=f"(lo), "=f"(hi) : "l"(v));
}
__device__ __forceinline__ float tanh_ap(float x) {
    float y;
    asm("tanh.approx.f32 %0, %1;" : "=f"(y) : "f"(x));
    return y;
}
__device__ __forceinline__ u64 tanh2(u64 v) {
    float lo, hi;
    unpack2(v, lo, hi);
    return pack2(tanh_ap(lo), tanh_ap(hi));
}

// ---------------- constant weight table (u64 units, weights duplicated (w,w)) ----------------
// Scalar compile-time-indexed accesses only -> ptxas emits LDCU (uniform port,
// floor 1/SMSP). NO vector loads: GPR-dest LDC.128 runs on the half-rate
// constant port (floor 8) and regressed R4.
enum {
    O_W1 = 0,           // 16x8  = 128
    O_B1 = 128,         // 16
    O_W2 = 144,         // 16x16 = 256
    O_B2 = 400,         // 16
    O_W3 = 416,         // 12x16 = 192
    O_B3 = 608,         // 12
    O_W4 = 620,         // 8x12  = 96
    O_B4 = 716,         // 8
    O_W5 = 724,         // 4x8   = 32
    O_B5 = 756,         // 4
    O_WH = 760,         // 4x4   = 16
    O_BH = 776,         // 4
    W_TOTAL = 780
};

struct CParams {
    u64   W[W_TOTAL];
    float F[21];        // Wf(18) + bf(2) + (-gamma*log2e)(1)
    float pad[3];
};

__constant__ CParams cP;
__device__ CParams gScratch;

#define LOG2E 1.4426950408889634f
#define LN2   0.6931471805599453f

// ---------------- prep kernel: build duplicated table in device scratch ----------------
__global__ void prep_kernel(
    const float* __restrict__ W1, const float* __restrict__ b1,
    const float* __restrict__ W2, const float* __restrict__ b2,
    const float* __restrict__ W3, const float* __restrict__ b3,
    const float* __restrict__ W4, const float* __restrict__ b4,
    const float* __restrict__ W5, const float* __restrict__ b5,
    const float* __restrict__ Wh, const float* __restrict__ bh,
    const float* __restrict__ Wf, const float* __restrict__ bf,
    const float* __restrict__ gamma)
{
    int tid = threadIdx.x;
#define CP_(off, src, n)                                       \
    for (int i = tid; i < (n); i += blockDim.x) {              \
        float f = (src)[i];                                    \
        gScratch.W[(off) + i] = pack2(f, f);                   \
    }
    CP_(O_W1, W1, 128); CP_(O_B1, b1, 16);
    CP_(O_W2, W2, 256); CP_(O_B2, b2, 16);
    CP_(O_W3, W3, 192); CP_(O_B3, b3, 12);
    CP_(O_W4, W4, 96);  CP_(O_B4, b4, 8);
    CP_(O_W5, W5, 32);  CP_(O_B5, b5, 4);
    CP_(O_WH, Wh, 16);  CP_(O_BH, bh, 4);
#undef CP_
    if (tid < 18) gScratch.F[tid] = Wf[tid];
    if (tid == 18) gScratch.F[18] = bf[0];
    if (tid == 19) gScratch.F[19] = bf[1];
    if (tid == 20) gScratch.F[20] = -gamma[0] * LOG2E;
}

// ---------------- dense layer on TWO packed pairs (4 samples) ----------------
// Each weight LDCU feeds two FFMA2s (pair0 + pair1). Scalar indices only.
template <int OFF_W, int OFF_B, int IN, int OUT, bool ACT>
__device__ __forceinline__ void layerfn(const u64* __restrict__ in0, const u64* __restrict__ in1,
                                        u64* __restrict__ out0, u64* __restrict__ out1) {
#pragma unroll
    for (int j = 0; j < OUT; j++) {
        u64 a0 = cP.W[OFF_B + j];
        u64 a1 = a0;
#pragma unroll
        for (int i = 0; i < IN; i++) {
            u64 w = cP.W[OFF_W + j * IN + i];
            a0 = ffma2(in0[i], w, a0);
            a1 = ffma2(in1[i], w, a1);
        }
        if (ACT) { a0 = tanh2(a0); a1 = tanh2(a1); }
        out0[j] = a0;
        out1[j] = a1;
    }
}

__global__ __launch_bounds__(128, 3) void qcnn_kernel(
    const float* __restrict__ x, float* __restrict__ out, int nb)
{
    int t = blockIdx.x * blockDim.x + threadIdx.x;
    int base = t * 4;                                // sample index, < 2^21
    if (base >= nb) return;
    const bool full = (base + 4 <= nb);

    // ---- load 4 samples (clamped for the tail) ----
    u64 A0[16], A1[16], B0[16], B1[16];
    {
        int s1 = (base + 1 < nb) ? base + 1 : nb - 1;
        int s2 = (base + 2 < nb) ? base + 2 : nb - 1;
        int s3 = (base + 3 < nb) ? base + 3 : nb - 1;
        const float4* p0 = (const float4*)(x + (size_t)base * 8);
        const float4* p1 = (const float4*)(x + (size_t)s1 * 8);
        const float4* p2 = (const float4*)(x + (size_t)s2 * 8);
        const float4* p3 = (const float4*)(x + (size_t)s3 * 8);
        float4 a = p0[0], b = p0[1];
        float4 c = p1[0], d = p1[1];
        float4 e = p2[0], f = p2[1];
        float4 g = p3[0], h = p3[1];
        A0[0] = pack2(a.x, c.x); A0[1] = pack2(a.y, c.y);
        A0[2] = pack2(a.z, c.z); A0[3] = pack2(a.w, c.w);
        A0[4] = pack2(b.x, d.x); A0[5] = pack2(b.y, d.y);
        A0[6] = pack2(b.z, d.z); A0[7] = pack2(b.w, d.w);
        A1[0] = pack2(e.x, g.x); A1[1] = pack2(e.y, g.y);
        A1[2] = pack2(e.z, g.z); A1[3] = pack2(e.w, g.w);
        A1[4] = pack2(f.x, h.x); A1[5] = pack2(f.y, h.y);
        A1[6] = pack2(f.z, h.z); A1[7] = pack2(f.w, h.w);
    }

    layerfn<O_W1, O_B1, 8,  16, true >(A0, A1, B0, B1);
    layerfn<O_W2, O_B2, 16, 16, true >(B0, B1, A0, A1);
    layerfn<O_W3, O_B3, 16, 12, true >(A0, A1, B0, B1);
    layerfn<O_W4, O_B4, 12, 8,  true >(B0, B1, A0, A1);
    layerfn<O_W5, O_B5, 8,  4,  true >(A0, A1, B0, B1);
    layerfn<O_WH, O_BH, 4,  4,  false>(B0, B1, A0, A1);   // cls_out in A0/A1[0..3]

    // ---- tail: RBF feature + final linear + log_softmax (scalar per sample) ----
    float cls[4][4];
#pragma unroll
    for (int j = 0; j < 4; j++) {
        unpack2(A0[j], cls[0][j], cls[1][j]);
        unpack2(A1[j], cls[2][j], cls[3][j]);
    }

    const float ngl2 = cP.F[20];
    float r[4][2];
#pragma unroll
    for (int s = 0; s < 4; s++) {
        float c0s = cls[s][0], c1s = cls[s][1], c2s = cls[s][2], c3s = cls[s][3];
        float s2 = fmaf(c0s, c0s, fmaf(c1s, c1s, fmaf(c2s, c2s, c3s * c3s)));
        float k = exp2f(s2 * ngl2);                         // exp(-gamma*s2)
        float o0 = cP.F[18];
        o0 = fmaf(cP.F[0], c0s, o0); o0 = fmaf(cP.F[1], c1s, o0);
        o0 = fmaf(cP.F[2], c2s, o0); o0 = fmaf(cP.F[3], c3s, o0);
        o0 = fmaf(cP.F[8], k, o0);
        float o1 = cP.F[19];
        o1 = fmaf(cP.F[9],  c0s, o1); o1 = fmaf(cP.F[10], c1s, o1);
        o1 = fmaf(cP.F[11], c2s, o1); o1 = fmaf(cP.F[12], c3s, o1);
        o1 = fmaf(cP.F[17], k, o1);

        float m  = fmaxf(o0, o1);
        float mn = fminf(o0, o1);
        float tt = exp2f((mn - m) * LOG2E);
        float lg; asm("lg2.approx.f32 %0, %1;" : "=f"(lg) : "f"(1.0f + tt));
        float lse = m + lg * LN2;
        r[s][0] = o0 - lse;
        r[s][1] = o1 - lse;
    }

    if (full) {
        float4 v0 = make_float4(r[0][0], r[0][1], r[1][0], r[1][1]);
        float4 v1 = make_float4(r[2][0], r[2][1], r[3][0], r[3][1]);
        float4* po = (float4*)(out + (size_t)base * 2);
        po[0] = v0;
        po[1] = v1;
    } else {
#pragma unroll
        for (int s = 0; s < 4; s++) {
            if (base + s < nb) {
                out[(base + s) * 2 + 0] = r[s][0];
                out[(base + s) * 2 + 1] = r[s][1];
            }
        }
    }
}

extern "C" void kernel_launch(void* const* d_in, const int* in_sizes, int n_in,
                              void* d_out, int out_size) {
    const float* x  = (const float*)d_in[0];
    const float* W1 = (const float*)d_in[1];
    const float* b1 = (const float*)d_in[2];
    const float* W2 = (const float*)d_in[3];
    const float* b2 = (const float*)d_in[4];
    const float* W3 = (const float*)d_in[5];
    const float* b3 = (const float*)d_in[6];
    const float* W4 = (const float*)d_in[7];
    const float* b4 = (const float*)d_in[8];
    const float* W5 = (const float*)d_in[9];
    const float* b5 = (const float*)d_in[10];
    const float* Wh = (const float*)d_in[11];
    const float* bh = (const float*)d_in[12];
    const float* Wf = (const float*)d_in[13];
    const float* bf = (const float*)d_in[14];
    const float* gm = (const float*)d_in[15];

    // 1) build duplicated weight table in device scratch
    prep_kernel<<<1, 256>>>(W1, b1, W2, b2, W3, b3, W4, b4, W5, b5,
                            Wh, bh, Wf, bf, gm);

    // 2) move it into the constant bank (D2D async copy — graph-capturable)
    void* scratch_addr = nullptr;
    cudaGetSymbolAddress(&scratch_addr, gScratch);
    cudaMemcpyToSymbolAsync(cP, scratch_addr, sizeof(CParams), 0,
                            cudaMemcpyDeviceToDevice, 0);

    // 3) main kernel
    int nb = in_sizes[0] / 8;
    int threads = 128;
    int spb = threads * 4;
    int blocks = (nb + spb - 1) / spb;
    qcnn_kernel<<<blocks, threads>>>(x, (float*)d_out, nb);
}

// round 6
// speedup vs baseline: 1.1518x; 1.0056x over previous
#include <cuda_runtime.h>

typedef unsigned long long u64;

// ---------------- packed f32x2 helpers (sm_10x) ----------------
__device__ __forceinline__ u64 ffma2(u64 a, u64 b, u64 c) {
    u64 d;
    asm("fma.rn.f32x2 %0, %1, %2, %3;" : "=l"(d) : "l"(a), "l"(b), "l"(c));
    return d;
}
__device__ __forceinline__ u64 pack2(float lo, float hi) {
    u64 r;
    asm("mov.b64 %0, {%1, %2};" : "=l"(r) : "f"(lo), "f"(hi));
    return r;
}
__device__ __forceinline__ void unpack2(u64 v, float& lo, float& hi) {
    asm("mov.b64 {%0, %1}, %2;" : "=f"(lo), "=f"(hi) : "l"(v));
}
__device__ __forceinline__ float tanh_ap(float x) {
    float y;
    asm("tanh.approx.f32 %0, %1;" : "=f"(y) : "f"(x));
    return y;
}
__device__ __forceinline__ u64 tanh2(u64 v) {
    float lo, hi;
    unpack2(v, lo, hi);
    return pack2(tanh_ap(lo), tanh_ap(hi));
}

// ---------------- constant weight table (u64 units, weights duplicated (w,w)) ----------------
// Scalar compile-time-indexed accesses only -> LDCU (uniform port, floor 1).
// NO vector constant loads (GPR-dest LDC.128 = half-rate port, regressed R4).
enum {
    O_W1 = 0,           // 16x8  = 128
    O_B1 = 128,         // 16
    O_W2 = 144,         // 16x16 = 256
    O_B2 = 400,         // 16
    O_W3 = 416,         // 12x16 = 192
    O_B3 = 608,         // 12
    O_W4 = 620,         // 8x12  = 96
    O_B4 = 716,         // 8
    O_W5 = 724,         // 4x8   = 32
    O_B5 = 756,         // 4
    O_WH = 760,         // 4x4   = 16
    O_BH = 776,         // 4
    W_TOTAL = 780
};

struct CParams {
    u64   W[W_TOTAL];
    float F[21];        // Wf(18) + bf(2) + (-gamma*log2e)(1)
    float pad[3];
};

__constant__ CParams cP;
__device__ CParams gScratch;

#define LOG2E 1.4426950408889634f
#define LN2   0.6931471805599453f

// ---------------- prep kernel: build duplicated table in device scratch ----------------
__global__ void prep_kernel(
    const float* __restrict__ W1, const float* __restrict__ b1,
    const float* __restrict__ W2, const float* __restrict__ b2,
    const float* __restrict__ W3, const float* __restrict__ b3,
    const float* __restrict__ W4, const float* __restrict__ b4,
    const float* __restrict__ W5, const float* __restrict__ b5,
    const float* __restrict__ Wh, const float* __restrict__ bh,
    const float* __restrict__ Wf, const float* __restrict__ bf,
    const float* __restrict__ gamma)
{
    int tid = threadIdx.x;
#define CP_(off, src, n)                                       \
    for (int i = tid; i < (n); i += blockDim.x) {              \
        float f = (src)[i];                                    \
        gScratch.W[(off) + i] = pack2(f, f);                   \
    }
    CP_(O_W1, W1, 128); CP_(O_B1, b1, 16);
    CP_(O_W2, W2, 256); CP_(O_B2, b2, 16);
    CP_(O_W3, W3, 192); CP_(O_B3, b3, 12);
    CP_(O_W4, W4, 96);  CP_(O_B4, b4, 8);
    CP_(O_W5, W5, 32);  CP_(O_B5, b5, 4);
    CP_(O_WH, Wh, 16);  CP_(O_BH, bh, 4);
#undef CP_
    if (tid < 18) gScratch.F[tid] = Wf[tid];
    if (tid == 18) gScratch.F[18] = bf[0];
    if (tid == 19) gScratch.F[19] = bf[1];
    if (tid == 20) gScratch.F[20] = -gamma[0] * LOG2E;
}

// ---------------- dense layer on TWO packed pairs (4 samples) ----------------
// Each weight LDCU feeds two FFMA2s (pair0 + pair1). Scalar indices only.
template <int OFF_W, int OFF_B, int IN, int OUT, bool ACT>
__device__ __forceinline__ void layerfn(const u64* __restrict__ in0, const u64* __restrict__ in1,
                                        u64* __restrict__ out0, u64* __restrict__ out1) {
#pragma unroll
    for (int j = 0; j < OUT; j++) {
        u64 a0 = cP.W[OFF_B + j];
        u64 a1 = a0;
#pragma unroll
        for (int i = 0; i < IN; i++) {
            u64 w = cP.W[OFF_W + j * IN + i];
            a0 = ffma2(in0[i], w, a0);
            a1 = ffma2(in1[i], w, a1);
        }
        if (ACT) { a0 = tanh2(a0); a1 = tanh2(a1); }
        out0[j] = a0;
        out1[j] = a1;
    }
}

__global__ __launch_bounds__(128, 4) void qcnn_kernel(
    const float* __restrict__ x, float* __restrict__ out, int nb)
{
    int t = blockIdx.x * blockDim.x + threadIdx.x;
    int base = t * 4;                                // sample index, < 2^21
    if (base >= nb) return;
    const bool full = (base + 4 <= nb);

    // ---- load 4 samples (clamped for the tail) ----
    u64 A0[16], A1[16], B0[16], B1[16];
    {
        int s1 = (base + 1 < nb) ? base + 1 : nb - 1;
        int s2 = (base + 2 < nb) ? base + 2 : nb - 1;
        int s3 = (base + 3 < nb) ? base + 3 : nb - 1;
        const float4* p0 = (const float4*)(x + (size_t)base * 8);
        const float4* p1 = (const float4*)(x + (size_t)s1 * 8);
        const float4* p2 = (const float4*)(x + (size_t)s2 * 8);
        const float4* p3 = (const float4*)(x + (size_t)s3 * 8);
        float4 a = p0[0], b = p0[1];
        float4 c = p1[0], d = p1[1];
        float4 e = p2[0], f = p2[1];
        float4 g = p3[0], h = p3[1];
        A0[0] = pack2(a.x, c.x); A0[1] = pack2(a.y, c.y);
        A0[2] = pack2(a.z, c.z); A0[3] = pack2(a.w, c.w);
        A0[4] = pack2(b.x, d.x); A0[5] = pack2(b.y, d.y);
        A0[6] = pack2(b.z, d.z); A0[7] = pack2(b.w, d.w);
        A1[0] = pack2(e.x, g.x); A1[1] = pack2(e.y, g.y);
        A1[2] = pack2(e.z, g.z); A1[3] = pack2(e.w, g.w);
        A1[4] = pack2(f.x, h.x); A1[5] = pack2(f.y, h.y);
        A1[6] = pack2(f.z, h.z); A1[7] = pack2(f.w, h.w);
    }

    layerfn<O_W1, O_B1, 8,  16, true >(A0, A1, B0, B1);
    layerfn<O_W2, O_B2, 16, 16, true >(B0, B1, A0, A1);
    layerfn<O_W3, O_B3, 16, 12, true >(A0, A1, B0, B1);
    layerfn<O_W4, O_B4, 12, 8,  true >(B0, B1, A0, A1);
    layerfn<O_W5, O_B5, 8,  4,  true >(A0, A1, B0, B1);
    layerfn<O_WH, O_BH, 4,  4,  false>(B0, B1, A0, A1);   // cls_out in A0/A1[0..3]

    // ---- tail: RBF feature + final linear + log_softmax, per sample ----
    const float ngl2 = cP.F[20];
    float r[4][2];
#pragma unroll
    for (int s = 0; s < 4; s++) {
        const u64* Ap = (s < 2) ? A0 : A1;
        float c0s, c1s, c2s, c3s, dummy;
        if ((s & 1) == 0) {
            unpack2(Ap[0], c0s, dummy); unpack2(Ap[1], c1s, dummy);
            unpack2(Ap[2], c2s, dummy); unpack2(Ap[3], c3s, dummy);
        } else {
            unpack2(Ap[0], dummy, c0s); unpack2(Ap[1], dummy, c1s);
            unpack2(Ap[2], dummy, c2s); unpack2(Ap[3], dummy, c3s);
        }
        float s2 = fmaf(c0s, c0s, fmaf(c1s, c1s, fmaf(c2s, c2s, c3s * c3s)));
        float k = exp2f(s2 * ngl2);                         // exp(-gamma*s2)
        float o0 = cP.F[18];
        o0 = fmaf(cP.F[0], c0s, o0); o0 = fmaf(cP.F[1], c1s, o0);
        o0 = fmaf(cP.F[2], c2s, o0); o0 = fmaf(cP.F[3], c3s, o0);
        o0 = fmaf(cP.F[8], k, o0);
        float o1 = cP.F[19];
        o1 = fmaf(cP.F[9],  c0s, o1); o1 = fmaf(cP.F[10], c1s, o1);
        o1 = fmaf(cP.F[11], c2s, o1); o1 = fmaf(cP.F[12], c3s, o1);
        o1 = fmaf(cP.F[17], k, o1);

        float m  = fmaxf(o0, o1);
        float mn = fminf(o0, o1);
        float tt = exp2f((mn - m) * LOG2E);
        float lg; asm("lg2.approx.f32 %0, %1;" : "=f"(lg) : "f"(1.0f + tt));
        float lse = m + lg * LN2;
        r[s][0] = o0 - lse;
        r[s][1] = o1 - lse;
    }

    if (full) {
        float4 v0 = make_float4(r[0][0], r[0][1], r[1][0], r[1][1]);
        float4 v1 = make_float4(r[2][0], r[2][1], r[3][0], r[3][1]);
        float4* po = (float4*)(out + (size_t)base * 2);
        po[0] = v0;
        po[1] = v1;
    } else {
#pragma unroll
        for (int s = 0; s < 4; s++) {
            if (base + s < nb) {
                out[(base + s) * 2 + 0] = r[s][0];
                out[(base + s) * 2 + 1] = r[s][1];
            }
        }
    }
}

extern "C" void kernel_launch(void* const* d_in, const int* in_sizes, int n_in,
                              void* d_out, int out_size) {
    const float* x  = (const float*)d_in[0];
    const float* W1 = (const float*)d_in[1];
    const float* b1 = (const float*)d_in[2];
    const float* W2 = (const float*)d_in[3];
    const float* b2 = (const float*)d_in[4];
    const float* W3 = (const float*)d_in[5];
    const float* b3 = (const float*)d_in[6];
    const float* W4 = (const float*)d_in[7];
    const float* b4 = (const float*)d_in[8];
    const float* W5 = (const float*)d_in[9];
    const float* b5 = (const float*)d_in[10];
    const float* Wh = (const float*)d_in[11];
    const float* bh = (const float*)d_in[12];
    const float* Wf = (const float*)d_in[13];
    const float* bf = (const float*)d_in[14];
    const float* gm = (const float*)d_in[15];

    // 1) build duplicated weight table in device scratch
    prep_kernel<<<1, 256>>>(W1, b1, W2, b2, W3, b3, W4, b4, W5, b5,
                            Wh, bh, Wf, bf, gm);

    // 2) move it into the constant bank (D2D async copy — graph-capturable)
    void* scratch_addr = nullptr;
    cudaGetSymbolAddress(&scratch_addr, gScratch);
    cudaMemcpyToSymbolAsync(cP, scratch_addr, sizeof(CParams), 0,
                            cudaMemcpyDeviceToDevice, 0);

    // 3) main kernel
    int nb = in_sizes[0] / 8;
    int threads = 128;
    int spb = threads * 4;
    int blocks = (nb + spb - 1) / spb;
    qcnn_kernel<<<blocks, threads>>>(x, (float*)d_out, nb);
}